// round 3
// baseline (speedup 1.0000x reference)
#include <cuda_runtime.h>
#include <cuda_bf16.h>

#define BATCH 4
#define CDIM  256
#define NDIM  4096
#define OC3   768
#define SA    20   // smem row stride in uint32 (16 k-pairs + pad; cp.async 16B-aligned)

// Scratch (static device globals — no allocations allowed)
__device__ __nv_bfloat16 g_xb   [(size_t)BATCH * CDIM * NDIM];
__device__ __nv_bfloat16 g_wqkvb[(size_t)OC3 * CDIM];
__device__ __nv_bfloat16 g_wprjb[(size_t)CDIM * CDIM];
__device__ __nv_bfloat16 g_qkv  [(size_t)BATCH * OC3 * NDIM];   // [b][o][n] Q|K|V
__device__ float         g_scores[(size_t)BATCH * NDIM * NDIM]; // fp32 pre-softmax
__device__ __nv_bfloat16 g_probs [(size_t)BATCH * NDIM * NDIM]; // bf16 post-softmax
__device__ __nv_bfloat16 g_attn [(size_t)BATCH * CDIM * NDIM];

__device__ __forceinline__ void cp16(void* smem_dst, const void* gsrc) {
    unsigned s = (unsigned)__cvta_generic_to_shared(smem_dst);
    asm volatile("cp.async.cg.shared.global [%0], [%1], 16;" :: "r"(s), "l"(gsrc));
}
__device__ __forceinline__ void cp_wait() {
    asm volatile("cp.async.commit_group;\n cp.async.wait_group 0;" ::: "memory");
}

__device__ __forceinline__ void mma16(float c[4], const unsigned a[4], const unsigned b[2]) {
    asm volatile(
        "mma.sync.aligned.m16n8k16.row.col.f32.bf16.bf16.f32 "
        "{%0,%1,%2,%3}, {%4,%5,%6,%7}, {%8,%9}, {%0,%1,%2,%3};"
        : "+f"(c[0]), "+f"(c[1]), "+f"(c[2]), "+f"(c[3])
        : "r"(a[0]), "r"(a[1]), "r"(a[2]), "r"(a[3]), "r"(b[0]), "r"(b[1]));
}

// ---------------------------------------------------------------------------
// fp32 -> bf16 conversion (grid-stride over float4 groups)
// ---------------------------------------------------------------------------
__global__ void f2b(const float* __restrict__ s, __nv_bfloat16* __restrict__ d, int n4) {
    int i = blockIdx.x * blockDim.x + threadIdx.x;
    if (i < n4) {
        float4 v = ((const float4*)s)[i];
        ((__nv_bfloat162*)d)[2 * i]     = __float22bfloat162_rn(make_float2(v.x, v.y));
        ((__nv_bfloat162*)d)[2 * i + 1] = __float22bfloat162_rn(make_float2(v.z, v.w));
    }
}

// ---------------------------------------------------------------------------
// bf16 tensor-core GEMM: C[m][n] = epi( sum_k A(m,k) * B(k,n) )
// Block tile 128x128, K-chunk 32. 8 warps = 4(M) x 2(N), warp tile 32x64.
// Smem always [m][k-pair] uint32, stride SA=20 (conflict-free frags + cp.async).
// AKC/BKC: operand k-contiguous in gmem -> cp.async copy; else scatter fill.
// EPI: 0 plain | 1 *scale | 2 +bias[m] | 3 +bias[m]+X residual.  OUTBF: bf16 C.
// ---------------------------------------------------------------------------
template<bool AKC, bool BKC, int EPI, bool OUTBF>
__global__ void __launch_bounds__(256, 2) gemm_bf16(
    const __nv_bfloat16* __restrict__ A, long am, long ak, long aB,
    const __nv_bfloat16* __restrict__ B, long bk, long bn, long bB,
    void* __restrict__ Cv, long cB,
    int KT, float scale,
    const float* __restrict__ bias,
    const float* __restrict__ X, long xB)
{
    __shared__ __align__(16) unsigned As[128 * SA];
    __shared__ __align__(16) unsigned Bs[128 * SA];

    const int bz = blockIdx.z;
    const int M0 = blockIdx.y * 128;
    const int N0 = blockIdx.x * 128;
    A += (size_t)bz * aB;
    B += (size_t)bz * bB;

    const int tid  = threadIdx.x;
    const int wid  = tid >> 5;
    const int lane = tid & 31;
    const int g    = lane >> 2;
    const int tg   = lane & 3;
    const int wm   = (wid & 3) * 32;
    const int wn   = (wid >> 2) * 64;

    float c[2][8][4];
    #pragma unroll
    for (int mt = 0; mt < 2; mt++)
        #pragma unroll
        for (int nt = 0; nt < 8; nt++)
            #pragma unroll
            for (int e = 0; e < 4; e++) c[mt][nt][e] = 0.f;

    for (int kk0 = 0; kk0 < KT; kk0 += 32) {
        // ---- A tile ----
        if (AKC) {
            #pragma unroll
            for (int e = tid; e < 512; e += 256) {
                int m = e >> 2, q = e & 3;
                cp16(As + m * SA + q * 4, A + (size_t)(M0 + m) * am + kk0 + q * 8);
            }
        } else {
            __nv_bfloat16* Asb = (__nv_bfloat16*)As;
            #pragma unroll
            for (int e = tid; e < 512; e += 256) {
                int k = e >> 4, mg = e & 15;
                uint4 v = *(const uint4*)(A + (size_t)(kk0 + k) * ak + M0 + mg * 8);
                const __nv_bfloat16* p = (const __nv_bfloat16*)&v;
                #pragma unroll
                for (int i = 0; i < 8; i++) Asb[(mg * 8 + i) * (2 * SA) + k] = p[i];
            }
        }
        // ---- B tile ----
        if (BKC) {
            #pragma unroll
            for (int e = tid; e < 512; e += 256) {
                int n = e >> 2, q = e & 3;
                cp16(Bs + n * SA + q * 4, B + (size_t)(N0 + n) * bn + kk0 + q * 8);
            }
        } else {
            __nv_bfloat16* Bsb = (__nv_bfloat16*)Bs;
            #pragma unroll
            for (int e = tid; e < 512; e += 256) {
                int k = e >> 4, ng = e & 15;
                uint4 v = *(const uint4*)(B + (size_t)(kk0 + k) * bk + N0 + ng * 8);
                const __nv_bfloat16* p = (const __nv_bfloat16*)&v;
                #pragma unroll
                for (int i = 0; i < 8; i++) Bsb[(ng * 8 + i) * (2 * SA) + k] = p[i];
            }
        }
        if (AKC || BKC) cp_wait();
        __syncthreads();

        // ---- 2 k-steps of 16 ----
        #pragma unroll
        for (int ks = 0; ks < 2; ks++) {
            const int pb = ks * 8;
            unsigned a[2][4], b[8][2];
            #pragma unroll
            for (int mt = 0; mt < 2; mt++) {
                const int mrow = wm + mt * 16 + g;
                a[mt][0] = As[mrow * SA + pb + tg];
                a[mt][1] = As[(mrow + 8) * SA + pb + tg];
                a[mt][2] = As[mrow * SA + pb + tg + 4];
                a[mt][3] = As[(mrow + 8) * SA + pb + tg + 4];
            }
            #pragma unroll
            for (int nt = 0; nt < 8; nt++) {
                const int ncol = wn + nt * 8 + g;
                b[nt][0] = Bs[ncol * SA + pb + tg];
                b[nt][1] = Bs[ncol * SA + pb + tg + 4];
            }
            #pragma unroll
            for (int nt = 0; nt < 8; nt++)
                #pragma unroll
                for (int mt = 0; mt < 2; mt++)
                    mma16(c[mt][nt], a[mt], b[nt]);
        }
        __syncthreads();
    }

    // ---- epilogue ----
    float* Cf = (float*)Cv + (size_t)bz * cB;
    __nv_bfloat16* Cb = (__nv_bfloat16*)Cv + (size_t)bz * cB;
    if (EPI == 3) X += (size_t)bz * xB;

    #pragma unroll
    for (int mt = 0; mt < 2; mt++) {
        const int r0 = M0 + wm + mt * 16 + g;
        const int r1 = r0 + 8;
        float bv0 = 0.f, bv1 = 0.f;
        if (EPI >= 2) { bv0 = bias[r0]; bv1 = bias[r1]; }
        #pragma unroll
        for (int nt = 0; nt < 8; nt++) {
            const int col = N0 + wn + nt * 8 + 2 * tg;
            float v00 = c[mt][nt][0], v01 = c[mt][nt][1];
            float v10 = c[mt][nt][2], v11 = c[mt][nt][3];
            if (EPI == 1) { v00 *= scale; v01 *= scale; v10 *= scale; v11 *= scale; }
            if (EPI >= 2) { v00 += bv0; v01 += bv0; v10 += bv1; v11 += bv1; }
            if (EPI == 3) {
                const float2 x0 = *(const float2*)(X + (size_t)r0 * NDIM + col);
                const float2 x1 = *(const float2*)(X + (size_t)r1 * NDIM + col);
                v00 += x0.x; v01 += x0.y; v10 += x1.x; v11 += x1.y;
            }
            if (OUTBF) {
                *(__nv_bfloat162*)(Cb + (size_t)r0 * NDIM + col) =
                    __float22bfloat162_rn(make_float2(v00, v01));
                *(__nv_bfloat162*)(Cb + (size_t)r1 * NDIM + col) =
                    __float22bfloat162_rn(make_float2(v10, v11));
            } else {
                *(float2*)(Cf + (size_t)r0 * NDIM + col) = make_float2(v00, v01);
                *(float2*)(Cf + (size_t)r1 * NDIM + col) = make_float2(v10, v11);
            }
        }
    }
}

// ---------------------------------------------------------------------------
// Row softmax: fp32 scores in registers -> bf16 probs. 256 thr/row, 16 f/thr.
// ---------------------------------------------------------------------------
__global__ void softmax_rows(const float* __restrict__ S, __nv_bfloat16* __restrict__ P) {
    __shared__ float red[256];
    const size_t row = blockIdx.x;
    const float4* s4 = (const float4*)(S + row * NDIM);
    const int t = threadIdx.x;

    float4 v[4];
    float m = -1e30f;
    #pragma unroll
    for (int i = 0; i < 4; i++) {
        v[i] = s4[t + i * 256];
        m = fmaxf(m, fmaxf(fmaxf(v[i].x, v[i].y), fmaxf(v[i].z, v[i].w)));
    }
    red[t] = m;
    __syncthreads();
    for (int st = 128; st > 0; st >>= 1) {
        if (t < st) red[t] = fmaxf(red[t], red[t + st]);
        __syncthreads();
    }
    m = red[0];
    __syncthreads();

    float sum = 0.f;
    #pragma unroll
    for (int i = 0; i < 4; i++) {
        v[i].x = __expf(v[i].x - m);
        v[i].y = __expf(v[i].y - m);
        v[i].z = __expf(v[i].z - m);
        v[i].w = __expf(v[i].w - m);
        sum += (v[i].x + v[i].y) + (v[i].z + v[i].w);
    }
    red[t] = sum;
    __syncthreads();
    for (int st = 128; st > 0; st >>= 1) {
        if (t < st) red[t] += red[t + st];
        __syncthreads();
    }
    const float inv = 1.0f / red[0];

    __nv_bfloat162* p2 = (__nv_bfloat162*)(P + row * NDIM);
    #pragma unroll
    for (int i = 0; i < 4; i++) {
        const int j = t + i * 256;
        p2[2 * j]     = __float22bfloat162_rn(make_float2(v[i].x * inv, v[i].y * inv));
        p2[2 * j + 1] = __float22bfloat162_rn(make_float2(v[i].z * inv, v[i].w * inv));
    }
}

// ---------------------------------------------------------------------------
extern "C" void kernel_launch(void* const* d_in, const int* in_sizes, int n_in,
                              void* d_out, int out_size) {
    const float* x      = (const float*)d_in[0];
    const float* w_qkv  = (const float*)d_in[1];
    const float* b_qkv  = (const float*)d_in[2];
    const float* w_proj = (const float*)d_in[3];
    const float* b_proj = (const float*)d_in[4];
    float* out = (float*)d_out;

    __nv_bfloat16 *xb, *wqb, *wpb, *qkv, *probs, *attn;
    float *scores;
    cudaGetSymbolAddress((void**)&xb,     g_xb);
    cudaGetSymbolAddress((void**)&wqb,    g_wqkvb);
    cudaGetSymbolAddress((void**)&wpb,    g_wprjb);
    cudaGetSymbolAddress((void**)&qkv,    g_qkv);
    cudaGetSymbolAddress((void**)&scores, g_scores);
    cudaGetSymbolAddress((void**)&probs,  g_probs);
    cudaGetSymbolAddress((void**)&attn,   g_attn);

    // fp32 -> bf16 conversions
    {
        int n4 = (BATCH * CDIM * NDIM) / 4;
        f2b<<<(n4 + 255) / 256, 256>>>(x, xb, n4);
        n4 = (OC3 * CDIM) / 4;
        f2b<<<(n4 + 255) / 256, 256>>>(w_qkv, wqb, n4);
        n4 = (CDIM * CDIM) / 4;
        f2b<<<(n4 + 255) / 256, 256>>>(w_proj, wpb, n4);
    }

    // 1) QKV: C[o][n] = W[o][c] X[c][n] + b    (A k-contig; B n-contig)
    gemm_bf16<true, false, 2, true><<<dim3(NDIM / 128, OC3 / 128, BATCH), 256>>>(
        wqb, CDIM, 1, 0,
        xb, NDIM, 1, (long)CDIM * NDIM,
        qkv, (long)OC3 * NDIM,
        CDIM, 1.f, b_qkv, nullptr, 0);

    // 2) scores[i][j] = (1/16) Q[c][i]^T K[c][j]   (A m-contig; B n-contig)
    gemm_bf16<false, false, 1, false><<<dim3(NDIM / 128, NDIM / 128, BATCH), 256>>>(
        qkv, 1, NDIM, (long)OC3 * NDIM,
        qkv + (size_t)CDIM * NDIM, NDIM, 1, (long)OC3 * NDIM,
        scores, (long)NDIM * NDIM,
        CDIM, 0.0625f, nullptr, nullptr, 0);

    // 3) softmax fp32 -> bf16 probs
    softmax_rows<<<BATCH * NDIM, 256>>>(scores, probs);

    // 4) attn[c][i] = V[c][j] P[i][j]^T   (A k-contig; B k-contig)
    gemm_bf16<true, true, 0, true><<<dim3(NDIM / 128, CDIM / 128, BATCH), 256>>>(
        qkv + (size_t)2 * CDIM * NDIM, NDIM, 1, (long)OC3 * NDIM,
        probs, 1, NDIM, (long)NDIM * NDIM,
        attn, (long)CDIM * NDIM,
        NDIM, 1.f, nullptr, nullptr, 0);

    // 5) out = x + b + Wp attn   (A k-contig; B n-contig; fp32 out + residual)
    gemm_bf16<true, false, 3, false><<<dim3(NDIM / 128, CDIM / 128, BATCH), 256>>>(
        wpb, CDIM, 1, 0,
        attn, NDIM, 1, (long)CDIM * NDIM,
        out, (long)CDIM * NDIM,
        CDIM, 1.f, b_proj, x, (long)CDIM * NDIM);
}

// round 4
// speedup vs baseline: 2.4886x; 2.4886x over previous
#include <cuda_runtime.h>
#include <cuda_bf16.h>

#define BATCH 4
#define CDIM  256
#define NDIM  4096
#define OC3   768

// Scratch (static device globals — no allocations allowed)
__device__ __nv_bfloat16 g_xb   [(size_t)BATCH * CDIM * NDIM];
__device__ __nv_bfloat16 g_wqkvb[(size_t)OC3 * CDIM];
__device__ __nv_bfloat16 g_wprjb[(size_t)CDIM * CDIM];
__device__ __nv_bfloat16 g_qkv  [(size_t)BATCH * OC3 * NDIM];   // [b][o][n] Q|K|V
__device__ float         g_scores[(size_t)BATCH * NDIM * NDIM]; // fp32 pre-softmax
__device__ __nv_bfloat16 g_probs [(size_t)BATCH * NDIM * NDIM]; // bf16 post-softmax
__device__ __nv_bfloat16 g_attn [(size_t)BATCH * CDIM * NDIM];  // [b][c][i]

// ---------------------------------------------------------------------------
__device__ __forceinline__ void cp16(void* smem_dst, const void* gsrc) {
    unsigned s = (unsigned)__cvta_generic_to_shared(smem_dst);
    asm volatile("cp.async.cg.shared.global [%0], [%1], 16;" :: "r"(s), "l"(gsrc));
}
__device__ __forceinline__ void cp_commit() {
    asm volatile("cp.async.commit_group;" ::: "memory");
}
__device__ __forceinline__ void cp_wait1() {
    asm volatile("cp.async.wait_group 1;" ::: "memory");
}
__device__ __forceinline__ void cp_wait0() {
    asm volatile("cp.async.wait_group 0;" ::: "memory");
}

__device__ __forceinline__ void ldsm4(unsigned r[4], const void* p) {
    unsigned a = (unsigned)__cvta_generic_to_shared(p);
    asm volatile("ldmatrix.sync.aligned.m8n8.x4.shared.b16 {%0,%1,%2,%3}, [%4];"
                 : "=r"(r[0]), "=r"(r[1]), "=r"(r[2]), "=r"(r[3]) : "r"(a));
}
__device__ __forceinline__ void ldsm4t(unsigned r[4], const void* p) {
    unsigned a = (unsigned)__cvta_generic_to_shared(p);
    asm volatile("ldmatrix.sync.aligned.m8n8.x4.trans.shared.b16 {%0,%1,%2,%3}, [%4];"
                 : "=r"(r[0]), "=r"(r[1]), "=r"(r[2]), "=r"(r[3]) : "r"(a));
}

__device__ __forceinline__ void mma16(float c[4], const unsigned a[4],
                                      const unsigned b0, const unsigned b1) {
    asm volatile(
        "mma.sync.aligned.m16n8k16.row.col.f32.bf16.bf16.f32 "
        "{%0,%1,%2,%3}, {%4,%5,%6,%7}, {%8,%9}, {%0,%1,%2,%3};"
        : "+f"(c[0]), "+f"(c[1]), "+f"(c[2]), "+f"(c[3])
        : "r"(a[0]), "r"(a[1]), "r"(a[2]), "r"(a[3]), "r"(b0), "r"(b1));
}

// ---------------------------------------------------------------------------
// fp32 -> bf16 conversion (grid-stride over float4 groups)
// ---------------------------------------------------------------------------
__global__ void f2b(const float* __restrict__ s, __nv_bfloat16* __restrict__ d, int n4) {
    int i = blockIdx.x * blockDim.x + threadIdx.x;
    if (i < n4) {
        float4 v = ((const float4*)s)[i];
        ((__nv_bfloat162*)d)[2 * i]     = __float22bfloat162_rn(make_float2(v.x, v.y));
        ((__nv_bfloat162*)d)[2 * i + 1] = __float22bfloat162_rn(make_float2(v.z, v.w));
    }
}

// ---------------------------------------------------------------------------
// bf16 tensor-core GEMM: C[m][n] = epi( sum_k A(m,k) * B(k,n) )
// Block tile 128x128, K-chunk 32, 2-stage cp.async double buffer.
// 8 warps = 4(M) x 2(N); warp tile 32x64.
// ATR=0: A gmem k-contig, smem [m=128][k=32] stride 40 bf16, ldmatrix normal
// ATR=1: A gmem m-contig (k-major), smem [k=32][m=128] stride 136, ldmatrix.trans
// Same for BTR with n.
// EPI: 0 plain | 1 *scale | 2 +bias[m] | 3 +bias[m]+X residual.  OUTBF: bf16 C.
// ---------------------------------------------------------------------------
template<bool ATR, bool BTR, int EPI, bool OUTBF>
__global__ void __launch_bounds__(256, 2) gemm_bf16(
    const __nv_bfloat16* __restrict__ A, long lda, long aB,
    const __nv_bfloat16* __restrict__ B, long ldb, long bB,
    void* __restrict__ Cv, long cB,
    int KT, float scale,
    const float* __restrict__ bias,
    const float* __restrict__ X, long xB)
{
    constexpr int ASZ = ATR ? 32 * 136 : 128 * 40;
    constexpr int BSZ = BTR ? 32 * 136 : 128 * 40;
    __shared__ __align__(16) __nv_bfloat16 As[2][ASZ];
    __shared__ __align__(16) __nv_bfloat16 Bs[2][BSZ];

    const int bz = blockIdx.z;
    const int M0 = blockIdx.y * 128;
    const int N0 = blockIdx.x * 128;
    A += (size_t)bz * aB;
    B += (size_t)bz * bB;

    const int tid  = threadIdx.x;
    const int wid  = tid >> 5;
    const int lane = tid & 31;
    const int g    = lane >> 2;
    const int tg   = lane & 3;
    const int wm   = (wid & 3) * 32;
    const int wn   = (wid >> 2) * 64;

    // per-lane ldmatrix byte offsets within a stage buffer
    int offA[2], offB[4];
    #pragma unroll
    for (int mt = 0; mt < 2; mt++) {
        const int m0 = wm + mt * 16;
        if (!ATR)  // rows m, 80B stride; lanes0-15 rows m0..15, lanes16-31 +16B
            offA[mt] = (m0 + (lane & 15)) * 80 + ((lane >> 4) << 4);
        else       // rows k (272B); lanes: k = ((l>>4)<<3)+(l&7), m chunk by bit3
            offA[mt] = (((lane >> 4) << 3) + (lane & 7)) * 272
                     + m0 * 2 + (((lane >> 3) & 1) << 4);
    }
    #pragma unroll
    for (int nt2 = 0; nt2 < 4; nt2++) {
        const int n0 = wn + nt2 * 16;
        if (!BTR)  // rows n: lanes0-7 n0..7 k0, 8-15 n0..7 k16B, 16-31 n8..15
            offB[nt2] = (n0 + ((lane >> 4) << 3) + (lane & 7)) * 80
                      + (((lane >> 3) & 1) << 4);
        else       // rows k: lanes0-7 k0-7@n0, 8-15 k8-15@n0, 16-31 @n0+8
            offB[nt2] = ((((lane >> 3) & 1) << 3) + (lane & 7)) * 272
                      + (n0 + ((lane >> 4) << 3)) * 2;
    }
    constexpr int stepA = ATR ? 16 * 272 : 32;  // bytes per k16 step
    constexpr int stepB = BTR ? 16 * 272 : 32;

    float acc[2][8][4];
    #pragma unroll
    for (int mt = 0; mt < 2; mt++)
        #pragma unroll
        for (int nt = 0; nt < 8; nt++)
            #pragma unroll
            for (int e = 0; e < 4; e++) acc[mt][nt][e] = 0.f;

    auto load_stage = [&](int c, int st) {
        const int kk0 = c * 32;
        if (!ATR) {
            #pragma unroll
            for (int e = tid; e < 512; e += 256) {
                int m = e >> 2, q = e & 3;
                cp16(&As[st][m * 40 + q * 8], A + (size_t)(M0 + m) * lda + kk0 + q * 8);
            }
        } else {
            #pragma unroll
            for (int e = tid; e < 512; e += 256) {
                int k = e >> 4, q = e & 15;
                cp16(&As[st][k * 136 + q * 8], A + (size_t)(kk0 + k) * lda + M0 + q * 8);
            }
        }
        if (!BTR) {
            #pragma unroll
            for (int e = tid; e < 512; e += 256) {
                int n = e >> 2, q = e & 3;
                cp16(&Bs[st][n * 40 + q * 8], B + (size_t)(N0 + n) * ldb + kk0 + q * 8);
            }
        } else {
            #pragma unroll
            for (int e = tid; e < 512; e += 256) {
                int k = e >> 4, q = e & 15;
                cp16(&Bs[st][k * 136 + q * 8], B + (size_t)(kk0 + k) * ldb + N0 + q * 8);
            }
        }
        cp_commit();
    };

    const int nc = KT / 32;
    load_stage(0, 0);
    for (int c = 0; c < nc; c++) {
        const int st = c & 1;
        if (c + 1 < nc) { load_stage(c + 1, st ^ 1); cp_wait1(); }
        else            { cp_wait0(); }
        __syncthreads();

        const char* Ab = (const char*)As[st];
        const char* Bb = (const char*)Bs[st];
        #pragma unroll
        for (int ks = 0; ks < 2; ks++) {
            unsigned a[2][4];
            #pragma unroll
            for (int mt = 0; mt < 2; mt++) {
                if (!ATR) ldsm4 (a[mt], Ab + offA[mt] + ks * stepA);
                else      ldsm4t(a[mt], Ab + offA[mt] + ks * stepA);
            }
            #pragma unroll
            for (int nt2 = 0; nt2 < 4; nt2++) {
                unsigned b[4];
                if (!BTR) ldsm4 (b, Bb + offB[nt2] + ks * stepB);
                else      ldsm4t(b, Bb + offB[nt2] + ks * stepB);
                #pragma unroll
                for (int mt = 0; mt < 2; mt++) {
                    mma16(acc[mt][2 * nt2],     a[mt], b[0], b[1]);
                    mma16(acc[mt][2 * nt2 + 1], a[mt], b[2], b[3]);
                }
            }
        }
        __syncthreads();
    }

    // ---- epilogue ----
    float* Cf = (float*)Cv + (size_t)bz * cB;
    __nv_bfloat16* Cb = (__nv_bfloat16*)Cv + (size_t)bz * cB;
    if (EPI == 3) X += (size_t)bz * xB;

    #pragma unroll
    for (int mt = 0; mt < 2; mt++) {
        const int r0 = M0 + wm + mt * 16 + g;
        const int r1 = r0 + 8;
        float bv0 = 0.f, bv1 = 0.f;
        if (EPI >= 2) { bv0 = bias[r0]; bv1 = bias[r1]; }
        #pragma unroll
        for (int nt = 0; nt < 8; nt++) {
            const int col = N0 + wn + nt * 8 + 2 * tg;
            float v00 = acc[mt][nt][0], v01 = acc[mt][nt][1];
            float v10 = acc[mt][nt][2], v11 = acc[mt][nt][3];
            if (EPI == 1) { v00 *= scale; v01 *= scale; v10 *= scale; v11 *= scale; }
            if (EPI >= 2) { v00 += bv0; v01 += bv0; v10 += bv1; v11 += bv1; }
            if (EPI == 3) {
                const float2 x0 = *(const float2*)(X + (size_t)r0 * NDIM + col);
                const float2 x1 = *(const float2*)(X + (size_t)r1 * NDIM + col);
                v00 += x0.x; v01 += x0.y; v10 += x1.x; v11 += x1.y;
            }
            if (OUTBF) {
                *(__nv_bfloat162*)(Cb + (size_t)r0 * NDIM + col) =
                    __float22bfloat162_rn(make_float2(v00, v01));
                *(__nv_bfloat162*)(Cb + (size_t)r1 * NDIM + col) =
                    __float22bfloat162_rn(make_float2(v10, v11));
            } else {
                *(float2*)(Cf + (size_t)r0 * NDIM + col) = make_float2(v00, v01);
                *(float2*)(Cf + (size_t)r1 * NDIM + col) = make_float2(v10, v11);
            }
        }
    }
}

// ---------------------------------------------------------------------------
// Row softmax: fp32 scores -> bf16 probs. 256 thr/row, 16 floats/thread.
// ---------------------------------------------------------------------------
__global__ void softmax_rows(const float* __restrict__ S, __nv_bfloat16* __restrict__ P) {
    __shared__ float red[256];
    const size_t row = blockIdx.x;
    const float4* s4 = (const float4*)(S + row * NDIM);
    const int t = threadIdx.x;

    float4 v[4];
    float m = -1e30f;
    #pragma unroll
    for (int i = 0; i < 4; i++) {
        v[i] = s4[t + i * 256];
        m = fmaxf(m, fmaxf(fmaxf(v[i].x, v[i].y), fmaxf(v[i].z, v[i].w)));
    }
    red[t] = m;
    __syncthreads();
    for (int st = 128; st > 0; st >>= 1) {
        if (t < st) red[t] = fmaxf(red[t], red[t + st]);
        __syncthreads();
    }
    m = red[0];
    __syncthreads();

    float sum = 0.f;
    #pragma unroll
    for (int i = 0; i < 4; i++) {
        v[i].x = __expf(v[i].x - m);
        v[i].y = __expf(v[i].y - m);
        v[i].z = __expf(v[i].z - m);
        v[i].w = __expf(v[i].w - m);
        sum += (v[i].x + v[i].y) + (v[i].z + v[i].w);
    }
    red[t] = sum;
    __syncthreads();
    for (int st = 128; st > 0; st >>= 1) {
        if (t < st) red[t] += red[t + st];
        __syncthreads();
    }
    const float inv = 1.0f / red[0];

    __nv_bfloat162* p2 = (__nv_bfloat162*)(P + row * NDIM);
    #pragma unroll
    for (int i = 0; i < 4; i++) {
        const int j = t + i * 256;
        p2[2 * j]     = __float22bfloat162_rn(make_float2(v[i].x * inv, v[i].y * inv));
        p2[2 * j + 1] = __float22bfloat162_rn(make_float2(v[i].z * inv, v[i].w * inv));
    }
}

// ---------------------------------------------------------------------------
extern "C" void kernel_launch(void* const* d_in, const int* in_sizes, int n_in,
                              void* d_out, int out_size) {
    const float* x      = (const float*)d_in[0];
    const float* w_qkv  = (const float*)d_in[1];
    const float* b_qkv  = (const float*)d_in[2];
    const float* w_proj = (const float*)d_in[3];
    const float* b_proj = (const float*)d_in[4];
    float* out = (float*)d_out;

    __nv_bfloat16 *xb, *wqb, *wpb, *qkv, *probs, *attn;
    float *scores;
    cudaGetSymbolAddress((void**)&xb,     g_xb);
    cudaGetSymbolAddress((void**)&wqb,    g_wqkvb);
    cudaGetSymbolAddress((void**)&wpb,    g_wprjb);
    cudaGetSymbolAddress((void**)&qkv,    g_qkv);
    cudaGetSymbolAddress((void**)&scores, g_scores);
    cudaGetSymbolAddress((void**)&probs,  g_probs);
    cudaGetSymbolAddress((void**)&attn,   g_attn);

    {
        int n4 = (BATCH * CDIM * NDIM) / 4;
        f2b<<<(n4 + 255) / 256, 256>>>(x, xb, n4);
        n4 = (OC3 * CDIM) / 4;
        f2b<<<(n4 + 255) / 256, 256>>>(w_qkv, wqb, n4);
        n4 = (CDIM * CDIM) / 4;
        f2b<<<(n4 + 255) / 256, 256>>>(w_proj, wpb, n4);
    }

    // 1) QKV: C[o][n] = W[o][c] X[c][n] + b    (A KC; B k-major/n-contig)
    gemm_bf16<false, true, 2, true><<<dim3(NDIM / 128, OC3 / 128, BATCH), 256>>>(
        wqb, CDIM, 0,
        xb, NDIM, (long)CDIM * NDIM,
        qkv, (long)OC3 * NDIM,
        CDIM, 1.f, b_qkv, nullptr, 0);

    // 2) scores[i][j] = (1/16) Q[c][i]^T K[c][j]   (both k-major)
    gemm_bf16<true, true, 1, false><<<dim3(NDIM / 128, NDIM / 128, BATCH), 256>>>(
        qkv, NDIM, (long)OC3 * NDIM,
        qkv + (size_t)CDIM * NDIM, NDIM, (long)OC3 * NDIM,
        scores, (long)NDIM * NDIM,
        CDIM, 0.0625f, nullptr, nullptr, 0);

    // 3) softmax fp32 -> bf16 probs
    softmax_rows<<<BATCH * NDIM, 256>>>(scores, probs);

    // 4) attn[c][i] = V[c][j] P[i][j]^T   (both KC)
    gemm_bf16<false, false, 0, true><<<dim3(NDIM / 128, CDIM / 128, BATCH), 256>>>(
        qkv + (size_t)2 * CDIM * NDIM, NDIM, (long)OC3 * NDIM,
        probs, NDIM, (long)NDIM * NDIM,
        attn, (long)CDIM * NDIM,
        NDIM, 1.f, nullptr, nullptr, 0);

    // 5) out = x + b + Wp attn   (A KC; B k-major)
    gemm_bf16<false, true, 3, false><<<dim3(NDIM / 128, CDIM / 128, BATCH), 256>>>(
        wpb, CDIM, 0,
        attn, NDIM, (long)CDIM * NDIM,
        out, (long)CDIM * NDIM,
        CDIM, 1.f, b_proj, x, (long)CDIM * NDIM);
}